// round 13
// baseline (speedup 1.0000x reference)
#include <cuda_runtime.h>
#include <cuda_fp16.h>
#include <math.h>
#include <stdint.h>

#define S_LEN   2048
#define BATCH   2
#define HID     4096
#define NHEADS  32
#define HD      128
#define M_ROWS  (BATCH * S_LEN)     /* 4096 */
#define QKV_N   (3 * HID)           /* 12288 */
#define NEG_BIG (-1e30f)
#define SM_SCALE 0.088388347648318447f   /* 1/sqrt(128), folded into Q */

// ---------------------------------------------------------------------------
// Scratch (allocation-free rule: __device__ globals)
// ---------------------------------------------------------------------------
__device__ __align__(16) __half g_qf[(size_t)BATCH * NHEADS * S_LEN * HD];  // [b,h,s,d] scaled
__device__ __align__(16) __half g_kf[(size_t)BATCH * NHEADS * S_LEN * HD];
__device__ __align__(16) __half g_vf[(size_t)BATCH * NHEADS * S_LEN * HD];
__device__ __align__(16) __half g_x16[(size_t)M_ROWS * HID];      // x fp16
__device__ __align__(16) __half g_ctx16[(size_t)M_ROWS * HID];    // ctx fp16 (from flash)
__device__ __align__(16) __half g_wq[(size_t)QKV_N * HID];        // W_qkv^T [N,K] fp16
__device__ __align__(16) __half g_wo[(size_t)HID   * HID];        // W_o^T   [N,K] fp16

// ---------------------------------------------------------------------------
// helpers
// ---------------------------------------------------------------------------
__device__ __forceinline__ uint32_t su32(const void* p) {
    uint32_t a;
    asm("{ .reg .u64 t; cvta.to.shared.u64 t, %1; cvt.u32.u64 %0, t; }" : "=r"(a) : "l"(p));
    return a;
}
__device__ __forceinline__ void cpasync16(uint32_t saddr, const void* gaddr) {
    asm volatile("cp.async.cg.shared.global [%0], [%1], 16;" :: "r"(saddr), "l"(gaddr));
}
__device__ __forceinline__ void ldm_x4(uint32_t* r, uint32_t addr) {
    asm volatile("ldmatrix.sync.aligned.m8n8.x4.shared.b16 {%0,%1,%2,%3}, [%4];"
                 : "=r"(r[0]), "=r"(r[1]), "=r"(r[2]), "=r"(r[3]) : "r"(addr));
}
__device__ __forceinline__ void ldm_x4t(uint32_t* r, uint32_t addr) {
    asm volatile("ldmatrix.sync.aligned.m8n8.x4.trans.shared.b16 {%0,%1,%2,%3}, [%4];"
                 : "=r"(r[0]), "=r"(r[1]), "=r"(r[2]), "=r"(r[3]) : "r"(addr));
}
__device__ __forceinline__ void mma16816(float* c, const uint32_t* a, uint32_t b0, uint32_t b1) {
    asm volatile(
        "mma.sync.aligned.m16n8k16.row.col.f32.f16.f16.f32 "
        "{%0,%1,%2,%3}, {%4,%5,%6,%7}, {%8,%9}, {%0,%1,%2,%3};"
        : "+f"(c[0]), "+f"(c[1]), "+f"(c[2]), "+f"(c[3])
        : "r"(a[0]), "r"(a[1]), "r"(a[2]), "r"(a[3]), "r"(b0), "r"(b1));
}
__device__ __forceinline__ uint32_t packh2(float a, float b) {
    __half2 h = __floats2half2_rn(a, b);
    return *(uint32_t*)&h;
}

// ---------------------------------------------------------------------------
// Pack activations: fp32 -> fp16 (plain convert)
// ---------------------------------------------------------------------------
__global__ void pack_a(const float* __restrict__ in, __half* __restrict__ out, int n4)
{
    const int i = blockIdx.x * blockDim.x + threadIdx.x;
    if (i >= n4) return;
    const float4 f = ((const float4*)in)[i];
    __half2* p = (__half2*)out + (size_t)i * 2;
    p[0] = __floats2half2_rn(f.x, f.y);
    p[1] = __floats2half2_rn(f.z, f.w);
}

// ---------------------------------------------------------------------------
// Pack weights: fp32 [K, N] -> fp16 transposed [N, K]
// ---------------------------------------------------------------------------
__global__ void pack_w(const float* __restrict__ in, __half* __restrict__ outT, int N)
{
    __shared__ float t[32][33];
    const int nb = blockIdx.x * 32, kb = blockIdx.y * 32;
    const int tx = threadIdx.x, ty = threadIdx.y;
#pragma unroll
    for (int i = 0; i < 32; i += 8)
        t[ty + i][tx] = in[(size_t)(kb + ty + i) * N + nb + tx];
    __syncthreads();
#pragma unroll
    for (int i = 0; i < 32; i += 8) {
        const float f = t[tx][ty + i];
        outT[(size_t)(nb + ty + i) * HID + kb + tx] = __float2half(f);
    }
}

// ---------------------------------------------------------------------------
// Plain fp16 mma.sync GEMM over K=4096, 256x128 CTA tile, BK=32, 16 warps
// (8M x 2N of 32x64 warp tiles), 4-stage cp.async, 512 threads, 1 CTA/SM.
// Grid: x = M blocks (fastest -> A stays L2-resident), y = N blocks.
// MODE 0 (proj): fp32 C + bias.  MODE 1 (QKV): fp16 q/k/v [b,h,s,d], Q scaled.
// ---------------------------------------------------------------------------
#define A_TILE_B    20480u                 /* 256 rows x 80B */
#define B_TILE_B    10240u                 /* 128 rows x 80B */
#define GSTG        4
#define SLOT_BYTES  (A_TILE_B + B_TILE_B)  /* 30720 */
#define GEMM_DSMEM  (GSTG * SLOT_BYTES)    /* 122880 */

template<int MODE>
__global__ __launch_bounds__(512, 1)
void gemm_f16s(const __half* __restrict__ A, const __half* __restrict__ B,
               const float* __restrict__ bias, float* __restrict__ C, int Nd,
               __half* __restrict__ qf, __half* __restrict__ kf, __half* __restrict__ vf)
{
    extern __shared__ char smraw[];
    const uint32_t sbase = su32(smraw);

    const int tid  = threadIdx.x;
    const int lane = tid & 31, wid = tid >> 5;
    const int wm = (wid & 7) * 32, wn = (wid >> 3) * 64;
    const int m0 = blockIdx.x * 256, n0 = blockIdx.y * 128;
    const int nk = HID / 32;                       /* 128 chunks */

    const __half* Ag = A + (size_t)m0 * HID;
    const __half* Bg = B + (size_t)n0 * HID;

    const uint32_t aBase = (uint32_t)(wm + (lane & 15)) * 80u + (uint32_t)(lane >> 4) * 16u;
    const uint32_t bBase = A_TILE_B + (uint32_t)(wn + (lane & 15)) * 80u + (uint32_t)(lane >> 4) * 16u;

    float c[2][8][4];
#pragma unroll
    for (int i = 0; i < 2; i++)
#pragma unroll
        for (int j = 0; j < 8; j++)
#pragma unroll
            for (int q = 0; q < 4; q++) c[i][j][q] = 0.f;

    // cp.async mapping: chunk = 16B. A: 1024 chunks (2/thread). B: 512 chunks.
    auto issue = [&](int KT, int sl) {
        if (KT < nk) {
            const uint32_t st = sbase + (uint32_t)sl * SLOT_BYTES;
            {
                const int cA = tid;
                cpasync16(st + (uint32_t)(cA >> 2) * 80u + (uint32_t)(cA & 3) * 16u,
                          Ag + (size_t)(cA >> 2) * HID + KT * 32 + (cA & 3) * 8);
            }
            {
                const int cA = tid + 512;
                cpasync16(st + (uint32_t)(cA >> 2) * 80u + (uint32_t)(cA & 3) * 16u,
                          Ag + (size_t)(cA >> 2) * HID + KT * 32 + (cA & 3) * 8);
            }
            {
                const int cB = tid;
                cpasync16(st + A_TILE_B + (uint32_t)(cB >> 2) * 80u + (uint32_t)(cB & 3) * 16u,
                          Bg + (size_t)(cB >> 2) * HID + KT * 32 + (cB & 3) * 8);
            }
        }
        asm volatile("cp.async.commit_group;" ::: "memory");
    };

#pragma unroll
    for (int s = 0; s < GSTG - 1; s++) issue(s, s);

    int slot = 0;
#pragma unroll 1
    for (int kt = 0; kt < nk; kt++) {
        asm volatile("cp.async.wait_group %0;" :: "n"(GSTG - 2) : "memory");
        __syncthreads();
        {
            int ns = slot + GSTG - 1;
            if (ns >= GSTG) ns -= GSTG;
            issue(kt + GSTG - 1, ns);
        }

        const uint32_t sa = sbase + (uint32_t)slot * SLOT_BYTES;
#pragma unroll
        for (int kk = 0; kk < 2; kk++) {
            uint32_t A0[4], A1[4];
            ldm_x4(A0, sa + aBase + kk * 32u);
            ldm_x4(A1, sa + aBase + 1280u + kk * 32u);      /* +16 rows */
#pragma unroll
            for (int p = 0; p < 4; p++) {
                uint32_t Bq[4];
                ldm_x4(Bq, sa + bBase + (uint32_t)p * 1280u + kk * 32u);
                mma16816(c[0][2 * p],     A0, Bq[0], Bq[2]);
                mma16816(c[0][2 * p + 1], A0, Bq[1], Bq[3]);
                mma16816(c[1][2 * p],     A1, Bq[0], Bq[2]);
                mma16816(c[1][2 * p + 1], A1, Bq[1], Bq[3]);
            }
        }
        slot = (slot + 1 >= GSTG) ? 0 : slot + 1;
    }

    const int gg = lane >> 2, tt = (lane & 3) * 2;

    if (MODE == 0) {
#pragma unroll
        for (int nt = 0; nt < 8; nt++) {
            const int col = n0 + wn + nt * 8 + tt;
            const float2 bb = *(const float2*)(bias + col);
#pragma unroll
            for (int mt = 0; mt < 2; mt++) {
                const int row = m0 + wm + mt * 16 + gg;
                float2 v0, v1;
                v0.x = c[mt][nt][0] + bb.x;  v0.y = c[mt][nt][1] + bb.y;
                v1.x = c[mt][nt][2] + bb.x;  v1.y = c[mt][nt][3] + bb.y;
                *(float2*)(C + (size_t)row * Nd + col)       = v0;
                *(float2*)(C + (size_t)(row + 8) * Nd + col) = v1;
            }
        }
    } else {
        const int seg = n0 >> 12;               /* 0=q, 1=k, 2=v */
        const int h   = (n0 >> 7) & 31;
        __half* dst = (seg == 0) ? qf : (seg == 1) ? kf : vf;
        const float sc = (seg == 0) ? SM_SCALE : 1.0f;
#pragma unroll
        for (int nt = 0; nt < 8; nt++) {
            const int col = n0 + wn + nt * 8 + tt;
            const int d   = wn + nt * 8 + tt;
            const float2 bb = *(const float2*)(bias + col);
#pragma unroll
            for (int mt = 0; mt < 2; mt++) {
                const int row = m0 + wm + mt * 16 + gg;
#pragma unroll
                for (int half8 = 0; half8 < 2; half8++) {
                    const int tok = row + half8 * 8;
                    const int b = tok >> 11, s = tok & 2047;
                    const float v0 = (c[mt][nt][2 * half8 + 0] + bb.x) * sc;
                    const float v1 = (c[mt][nt][2 * half8 + 1] + bb.y) * sc;
                    __half2* p = (__half2*)(dst + (((size_t)(b * NHEADS + h) * S_LEN + s) * HD + d));
                    *p = __floats2half2_rn(v0, v1);
                }
            }
        }
    }
}

// ---------------------------------------------------------------------------
// Tensor-core flash attention: Br=128 (8 warps x 16 q-rows), Bc=64, fp32 acc,
// double-buffered K/V (2-stage cp.async ring).
// ---------------------------------------------------------------------------
#define QROW 272
#define KV_STAGE (2u * 64u * QROW)                       /* K+V per stage: 34816 */
#define FL_SMEM  (128 * QROW + 2 * (int)KV_STAGE)        /* 104448 */

__global__ __launch_bounds__(256, 2)
void flash_mma(const __half* __restrict__ Qf, const __half* __restrict__ Kf,
               const __half* __restrict__ Vf, __half* __restrict__ ctx16)
{
    extern __shared__ char sm8[];
    const uint32_t qs  = su32(sm8);
    const uint32_t kv0 = qs + 128 * QROW;                /* [K | V] stage 0 */

    const int tid = threadIdx.x, lane = tid & 31, wid = tid >> 5;
    const int bh = blockIdx.y, qb = blockIdx.x;
    const int g = lane >> 2, t = lane & 3;

    const __half* qg = Qf + ((size_t)bh * S_LEN + qb * 128) * HD;
    const __half* kg = Kf + (size_t)bh * S_LEN * HD;
    const __half* vg = Vf + (size_t)bh * S_LEN * HD;

    auto load_kv = [&](int j, int buf) {
        const uint32_t ks = kv0 + (uint32_t)buf * KV_STAGE;
        const uint32_t vs = ks + 64u * QROW;
        for (int i = tid; i < 1024; i += 256) {
            const int r = i >> 4, cc = i & 15;
            const size_t go = (size_t)(j * 64 + r) * HD + cc * 8;
            cpasync16(ks + r * QROW + cc * 16, kg + go);
            cpasync16(vs + r * QROW + cc * 16, vg + go);
        }
        asm volatile("cp.async.commit_group;" ::: "memory");
    };

    // Prologue: Q + KV(0) in group 0
    for (int i = tid; i < 2048; i += 256) {
        const int r = i >> 4, cc = i & 15;
        cpasync16(qs + r * QROW + cc * 16, qg + (size_t)r * HD + cc * 8);
    }
    {
        const uint32_t ks = kv0;
        const uint32_t vs = ks + 64u * QROW;
        for (int i = tid; i < 1024; i += 256) {
            const int r = i >> 4, cc = i & 15;
            const size_t go = (size_t)(r) * HD + cc * 8;
            cpasync16(ks + r * QROW + cc * 16, kg + go);
            cpasync16(vs + r * QROW + cc * 16, vg + go);
        }
    }
    asm volatile("cp.async.commit_group;" ::: "memory");

    float acc[16][4];
#pragma unroll
    for (int i = 0; i < 16; i++)
#pragma unroll
        for (int q = 0; q < 4; q++) acc[i][q] = 0.f;
    float m0 = NEG_BIG, m1 = NEG_BIG, l0 = 0.f, l1 = 0.f;

    const uint32_t aB = qs + (uint32_t)(wid * 16 + (lane & 15)) * QROW + (uint32_t)(lane >> 4) * 16u;
    const uint32_t bOff = (uint32_t)(lane & 15) * QROW + (uint32_t)(lane >> 4) * 16u;

    const int nj = S_LEN / 64;
#pragma unroll 1
    for (int j = 0; j < nj; j++) {
        if (j + 1 < nj) load_kv(j + 1, (j + 1) & 1);
        if (j + 1 < nj) {
            asm volatile("cp.async.wait_group 1;" ::: "memory");
        } else {
            asm volatile("cp.async.wait_group 0;" ::: "memory");
        }
        __syncthreads();

        const uint32_t ks = kv0 + (uint32_t)(j & 1) * KV_STAGE;
        const uint32_t vs = ks + 64u * QROW;
        const uint32_t bB = ks + bOff;
        const uint32_t vB = vs + bOff;

        float cs[8][4];
#pragma unroll
        for (int i = 0; i < 8; i++)
#pragma unroll
            for (int q = 0; q < 4; q++) cs[i][q] = 0.f;
#pragma unroll
        for (int kd = 0; kd < 8; kd++) {
            uint32_t Aq[4];
            ldm_x4(Aq, aB + kd * 32u);
#pragma unroll
            for (int p = 0; p < 4; p++) {
                uint32_t Bq[4];
                ldm_x4(Bq, bB + (uint32_t)p * 16u * QROW + kd * 32u);
                mma16816(cs[2 * p],     Aq, Bq[0], Bq[2]);
                mma16816(cs[2 * p + 1], Aq, Bq[1], Bq[3]);
            }
        }

        float rm0 = m0, rm1 = m1;
#pragma unroll
        for (int i = 0; i < 8; i++) {
            rm0 = fmaxf(rm0, fmaxf(cs[i][0], cs[i][1]));
            rm1 = fmaxf(rm1, fmaxf(cs[i][2], cs[i][3]));
        }
        rm0 = fmaxf(rm0, __shfl_xor_sync(0xffffffffu, rm0, 1));
        rm0 = fmaxf(rm0, __shfl_xor_sync(0xffffffffu, rm0, 2));
        rm1 = fmaxf(rm1, __shfl_xor_sync(0xffffffffu, rm1, 1));
        rm1 = fmaxf(rm1, __shfl_xor_sync(0xffffffffu, rm1, 2));
        const float al0 = __expf(m0 - rm0);
        const float al1 = __expf(m1 - rm1);
        m0 = rm0; m1 = rm1;

        uint32_t ph[8][2];
        float s0 = 0.f, s1 = 0.f;
#pragma unroll
        for (int i = 0; i < 8; i++) {
            const float e0 = __expf(cs[i][0] - m0);
            const float e1 = __expf(cs[i][1] - m0);
            const float e2 = __expf(cs[i][2] - m1);
            const float e3 = __expf(cs[i][3] - m1);
            s0 += e0 + e1;  s1 += e2 + e3;
            ph[i][0] = packh2(e0, e1);
            ph[i][1] = packh2(e2, e3);
        }
        s0 += __shfl_xor_sync(0xffffffffu, s0, 1);
        s0 += __shfl_xor_sync(0xffffffffu, s0, 2);
        s1 += __shfl_xor_sync(0xffffffffu, s1, 1);
        s1 += __shfl_xor_sync(0xffffffffu, s1, 2);
        l0 = l0 * al0 + s0;
        l1 = l1 * al1 + s1;

#pragma unroll
        for (int i = 0; i < 16; i++) {
            acc[i][0] *= al0; acc[i][1] *= al0;
            acc[i][2] *= al1; acc[i][3] *= al1;
        }

#pragma unroll
        for (int kc = 0; kc < 4; kc++) {
            uint32_t Ap[4] = { ph[2 * kc][0], ph[2 * kc][1], ph[2 * kc + 1][0], ph[2 * kc + 1][1] };
#pragma unroll
            for (int dn = 0; dn < 8; dn++) {
                uint32_t Bv[4];
                ldm_x4t(Bv, vB + (uint32_t)kc * 16u * QROW + (uint32_t)dn * 32u);
                mma16816(acc[2 * dn],     Ap, Bv[0], Bv[1]);
                mma16816(acc[2 * dn + 1], Ap, Bv[2], Bv[3]);
            }
        }
        __syncthreads();
    }

    // Epilogue: ctx plain fp16 [tok][h*128+d]
    const float il0 = 1.f / l0, il1 = 1.f / l1;
    const int b = bh >> 5, h = bh & 31;
    const int tok0 = b * S_LEN + qb * 128 + wid * 16 + g;
#pragma unroll
    for (int nt = 0; nt < 16; nt++) {
        const int d0 = (nt >> 1) * 16 + (nt & 1) * 8 + 2 * t;
#pragma unroll
        for (int half8 = 0; half8 < 2; half8++) {
            const int tok = tok0 + half8 * 8;
            const float il = half8 ? il1 : il0;
            const float v0 = acc[nt][2 * half8 + 0] * il;
            const float v1 = acc[nt][2 * half8 + 1] * il;
            *(__half2*)(ctx16 + (size_t)tok * HID + h * HD + d0) = __floats2half2_rn(v0, v1);
        }
    }
}

// ---------------------------------------------------------------------------
// Host side
// ---------------------------------------------------------------------------
extern "C" void kernel_launch(void* const* d_in, const int* in_sizes, int n_in,
                              void* d_out, int out_size)
{
    (void)in_sizes; (void)n_in; (void)out_size;
    const float* x    = (const float*)d_in[0];
    const float* qkvw = (const float*)d_in[1];
    const float* qkvb = (const float*)d_in[2];
    const float* ow   = (const float*)d_in[3];
    const float* ob   = (const float*)d_in[4];
    float* out = (float*)d_out;

    __half *qf, *kf, *vf, *x16, *ctx16, *wq, *wo;
    cudaGetSymbolAddress((void**)&qf,    g_qf);
    cudaGetSymbolAddress((void**)&kf,    g_kf);
    cudaGetSymbolAddress((void**)&vf,    g_vf);
    cudaGetSymbolAddress((void**)&x16,   g_x16);
    cudaGetSymbolAddress((void**)&ctx16, g_ctx16);
    cudaGetSymbolAddress((void**)&wq,    g_wq);
    cudaGetSymbolAddress((void**)&wo,    g_wo);

    cudaFuncSetAttribute(gemm_f16s<1>, cudaFuncAttributeMaxDynamicSharedMemorySize, GEMM_DSMEM);
    cudaFuncSetAttribute(gemm_f16s<0>, cudaFuncAttributeMaxDynamicSharedMemorySize, GEMM_DSMEM);
    cudaFuncSetAttribute(flash_mma, cudaFuncAttributeMaxDynamicSharedMemorySize, FL_SMEM);

    const int n4 = M_ROWS * HID / 4;

    // 1) pack x and weights to fp16
    pack_a<<<(n4 + 255) / 256, 256>>>(x, x16, n4);
    pack_w<<<dim3(QKV_N / 32, HID / 32), dim3(32, 8)>>>(qkvw, wq, QKV_N);
    pack_w<<<dim3(HID / 32, HID / 32), dim3(32, 8)>>>(ow, wo, HID);

    // 2) q,k,v (fp16, q pre-scaled) = x @ W_qkv + b   (grid: M fastest)
    gemm_f16s<1><<<dim3(M_ROWS / 256, QKV_N / 128), 512, GEMM_DSMEM>>>(
        x16, wq, qkvb, nullptr, QKV_N, qf, kf, vf);

    // 3) tensor-core flash attention -> ctx16 (fp16), double-buffered K/V
    flash_mma<<<dim3(S_LEN / 128, BATCH * NHEADS), 256, FL_SMEM>>>(qf, kf, vf, ctx16);

    // 4) out = ctx @ W_o + b
    gemm_f16s<0><<<dim3(M_ROWS / 256, HID / 128), 512, GEMM_DSMEM>>>(
        ctx16, wo, ob, out, HID, nullptr, nullptr, nullptr);
}

// round 15
// speedup vs baseline: 1.0805x; 1.0805x over previous
#include <cuda_runtime.h>
#include <cuda_fp16.h>
#include <math.h>
#include <stdint.h>

#define S_LEN   2048
#define BATCH   2
#define HID     4096
#define NHEADS  32
#define HD      128
#define M_ROWS  (BATCH * S_LEN)     /* 4096 */
#define QKV_N   (3 * HID)           /* 12288 */
#define NEG_BIG (-1e30f)
#define SM_SCALE 0.088388347648318447f   /* 1/sqrt(128), folded into Q */

// ---------------------------------------------------------------------------
// Scratch (allocation-free rule: __device__ globals)
// ---------------------------------------------------------------------------
__device__ __align__(16) __half g_qf[(size_t)BATCH * NHEADS * S_LEN * HD];  // [b,h,s,d] scaled
__device__ __align__(16) __half g_kf[(size_t)BATCH * NHEADS * S_LEN * HD];
__device__ __align__(16) __half g_vf[(size_t)BATCH * NHEADS * S_LEN * HD];
__device__ __align__(16) __half g_x16[(size_t)M_ROWS * HID];      // x fp16
__device__ __align__(16) __half g_ctx16[(size_t)M_ROWS * HID];    // ctx fp16 (from flash)
__device__ __align__(16) __half g_wq[(size_t)QKV_N * HID];        // W_qkv^T [N,K] fp16
__device__ __align__(16) __half g_wo[(size_t)HID   * HID];        // W_o^T   [N,K] fp16

// ---------------------------------------------------------------------------
// helpers
// ---------------------------------------------------------------------------
__device__ __forceinline__ uint32_t su32(const void* p) {
    uint32_t a;
    asm("{ .reg .u64 t; cvta.to.shared.u64 t, %1; cvt.u32.u64 %0, t; }" : "=r"(a) : "l"(p));
    return a;
}
__device__ __forceinline__ void cpasync16(uint32_t saddr, const void* gaddr) {
    asm volatile("cp.async.cg.shared.global [%0], [%1], 16;" :: "r"(saddr), "l"(gaddr));
}
__device__ __forceinline__ void ldm_x4(uint32_t* r, uint32_t addr) {
    asm volatile("ldmatrix.sync.aligned.m8n8.x4.shared.b16 {%0,%1,%2,%3}, [%4];"
                 : "=r"(r[0]), "=r"(r[1]), "=r"(r[2]), "=r"(r[3]) : "r"(addr));
}
__device__ __forceinline__ void ldm_x4t(uint32_t* r, uint32_t addr) {
    asm volatile("ldmatrix.sync.aligned.m8n8.x4.trans.shared.b16 {%0,%1,%2,%3}, [%4];"
                 : "=r"(r[0]), "=r"(r[1]), "=r"(r[2]), "=r"(r[3]) : "r"(addr));
}
__device__ __forceinline__ void mma16816(float* c, const uint32_t* a, uint32_t b0, uint32_t b1) {
    asm volatile(
        "mma.sync.aligned.m16n8k16.row.col.f32.f16.f16.f32 "
        "{%0,%1,%2,%3}, {%4,%5,%6,%7}, {%8,%9}, {%0,%1,%2,%3};"
        : "+f"(c[0]), "+f"(c[1]), "+f"(c[2]), "+f"(c[3])
        : "r"(a[0]), "r"(a[1]), "r"(a[2]), "r"(a[3]), "r"(b0), "r"(b1));
}
__device__ __forceinline__ uint32_t packh2(float a, float b) {
    __half2 h = __floats2half2_rn(a, b);
    return *(uint32_t*)&h;
}

// ---------------------------------------------------------------------------
// Pack activations: fp32 -> fp16 (plain convert)
// ---------------------------------------------------------------------------
__global__ void pack_a(const float* __restrict__ in, __half* __restrict__ out, int n4)
{
    const int i = blockIdx.x * blockDim.x + threadIdx.x;
    if (i >= n4) return;
    const float4 f = ((const float4*)in)[i];
    __half2* p = (__half2*)out + (size_t)i * 2;
    p[0] = __floats2half2_rn(f.x, f.y);
    p[1] = __floats2half2_rn(f.z, f.w);
}

// ---------------------------------------------------------------------------
// Pack weights: fp32 [K, N] -> fp16 transposed [N, K]
// ---------------------------------------------------------------------------
__global__ void pack_w(const float* __restrict__ in, __half* __restrict__ outT, int N)
{
    __shared__ float t[32][33];
    const int nb = blockIdx.x * 32, kb = blockIdx.y * 32;
    const int tx = threadIdx.x, ty = threadIdx.y;
#pragma unroll
    for (int i = 0; i < 32; i += 8)
        t[ty + i][tx] = in[(size_t)(kb + ty + i) * N + nb + tx];
    __syncthreads();
#pragma unroll
    for (int i = 0; i < 32; i += 8) {
        const float f = t[tx][ty + i];
        outT[(size_t)(nb + ty + i) * HID + kb + tx] = __float2half(f);
    }
}

// ---------------------------------------------------------------------------
// Plain fp16 mma.sync GEMM over K=4096, 128x128 CTA tile, BK=32, 8 warps,
// 4-stage cp.async, warp 32x64, 2 CTAs/SM (R12 known-best config).
// MODE 0 (proj): fp32 C + bias.  MODE 1 (QKV): fp16 q/k/v [b,h,s,d], Q scaled.
// ---------------------------------------------------------------------------
#define TILE_BYTES  10240u                 /* 128 rows x 80B */
#define GSTG        4
#define SLOT_BYTES  (2u * TILE_BYTES)      /* A + B */
#define GEMM_DSMEM  (GSTG * SLOT_BYTES)    /* 81920 */

template<int MODE>
__global__ __launch_bounds__(256, 2)
void gemm_f16s(const __half* __restrict__ A, const __half* __restrict__ B,
               const float* __restrict__ bias, float* __restrict__ C, int Nd,
               __half* __restrict__ qf, __half* __restrict__ kf, __half* __restrict__ vf)
{
    extern __shared__ char smraw[];
    const uint32_t sbase = su32(smraw);

    const int tid  = threadIdx.x;
    const int lane = tid & 31, wid = tid >> 5;
    const int wm = (wid & 3) * 32, wn = (wid >> 2) * 64;
    const int m0 = blockIdx.y * 128, n0 = blockIdx.x * 128;
    const int nk = HID / 32;                       /* 128 chunks */

    const __half* Ag = A + (size_t)m0 * HID;
    const __half* Bg = B + (size_t)n0 * HID;

    const int lrow = tid >> 2;                     /* 0..63 */
    const int lcol = (tid & 3) * 8;
    const uint32_t srowb = (uint32_t)lrow * 80u + (uint32_t)(tid & 3) * 16u;

    const uint32_t aBase = (uint32_t)(wm + (lane & 15)) * 80u + (uint32_t)(lane >> 4) * 16u;
    const uint32_t bBase = (uint32_t)(wn + (lane & 15)) * 80u + (uint32_t)(lane >> 4) * 16u;

    float c[2][8][4];
#pragma unroll
    for (int i = 0; i < 2; i++)
#pragma unroll
        for (int j = 0; j < 8; j++)
#pragma unroll
            for (int q = 0; q < 4; q++) c[i][j][q] = 0.f;

    auto issue = [&](int KT, int sl) {
        if (KT < nk) {
            const uint32_t st = sbase + (uint32_t)sl * SLOT_BYTES;
            const __half* ga = Ag + (size_t)lrow * HID + KT * 32 + lcol;
            const __half* gb = Bg + (size_t)lrow * HID + KT * 32 + lcol;
            cpasync16(st + srowb,                          ga);
            cpasync16(st + srowb + 64u * 80u,              ga + (size_t)64 * HID);
            cpasync16(st + TILE_BYTES + srowb,             gb);
            cpasync16(st + TILE_BYTES + srowb + 64u * 80u, gb + (size_t)64 * HID);
        }
        asm volatile("cp.async.commit_group;" ::: "memory");
    };

#pragma unroll
    for (int s = 0; s < GSTG - 1; s++) issue(s, s);

    int slot = 0;
#pragma unroll 1
    for (int kt = 0; kt < nk; kt++) {
        asm volatile("cp.async.wait_group %0;" :: "n"(GSTG - 2) : "memory");
        __syncthreads();
        {
            int ns = slot + GSTG - 1;
            if (ns >= GSTG) ns -= GSTG;
            issue(kt + GSTG - 1, ns);
        }

        const uint32_t sa = sbase + (uint32_t)slot * SLOT_BYTES;
        const uint32_t sb = sa + TILE_BYTES;
#pragma unroll
        for (int kk = 0; kk < 2; kk++) {
            uint32_t A0[4], A1[4];
            ldm_x4(A0, sa + aBase + kk * 32u);
            ldm_x4(A1, sa + aBase + 1280u + kk * 32u);      /* +16 rows */
#pragma unroll
            for (int p = 0; p < 4; p++) {
                uint32_t Bq[4];
                ldm_x4(Bq, sb + bBase + (uint32_t)p * 1280u + kk * 32u);
                mma16816(c[0][2 * p],     A0, Bq[0], Bq[2]);
                mma16816(c[0][2 * p + 1], A0, Bq[1], Bq[3]);
                mma16816(c[1][2 * p],     A1, Bq[0], Bq[2]);
                mma16816(c[1][2 * p + 1], A1, Bq[1], Bq[3]);
            }
        }
        slot = (slot + 1 >= GSTG) ? 0 : slot + 1;
    }

    const int gg = lane >> 2, tt = (lane & 3) * 2;

    if (MODE == 0) {
#pragma unroll
        for (int nt = 0; nt < 8; nt++) {
            const int col = n0 + wn + nt * 8 + tt;
            const float2 bb = *(const float2*)(bias + col);
#pragma unroll
            for (int mt = 0; mt < 2; mt++) {
                const int row = m0 + wm + mt * 16 + gg;
                float2 v0, v1;
                v0.x = c[mt][nt][0] + bb.x;  v0.y = c[mt][nt][1] + bb.y;
                v1.x = c[mt][nt][2] + bb.x;  v1.y = c[mt][nt][3] + bb.y;
                *(float2*)(C + (size_t)row * Nd + col)       = v0;
                *(float2*)(C + (size_t)(row + 8) * Nd + col) = v1;
            }
        }
    } else {
        const int seg = n0 >> 12;               /* 0=q, 1=k, 2=v */
        const int h   = (n0 >> 7) & 31;
        __half* dst = (seg == 0) ? qf : (seg == 1) ? kf : vf;
        const float sc = (seg == 0) ? SM_SCALE : 1.0f;
#pragma unroll
        for (int nt = 0; nt < 8; nt++) {
            const int col = n0 + wn + nt * 8 + tt;
            const int d   = wn + nt * 8 + tt;
            const float2 bb = *(const float2*)(bias + col);
#pragma unroll
            for (int mt = 0; mt < 2; mt++) {
                const int row = m0 + wm + mt * 16 + gg;
#pragma unroll
                for (int half8 = 0; half8 < 2; half8++) {
                    const int tok = row + half8 * 8;
                    const int b = tok >> 11, s = tok & 2047;
                    const float v0 = (c[mt][nt][2 * half8 + 0] + bb.x) * sc;
                    const float v1 = (c[mt][nt][2 * half8 + 1] + bb.y) * sc;
                    __half2* p = (__half2*)(dst + (((size_t)(b * NHEADS + h) * S_LEN + s) * HD + d));
                    *p = __floats2half2_rn(v0, v1);
                }
            }
        }
    }
}

// ---------------------------------------------------------------------------
// Tensor-core flash attention: Br=128 (8 warps x 16 q-rows), Bc=64, fp32 acc,
// double-buffered K/V (2-stage cp.async ring), 2 CTAs/SM.
// ---------------------------------------------------------------------------
#define QROW 272
#define KV_STAGE (2u * 64u * QROW)                       /* K+V per stage: 34816 */
#define FL_SMEM  (128 * QROW + 2 * (int)KV_STAGE)        /* 104448 */

__global__ __launch_bounds__(256, 2)
void flash_mma(const __half* __restrict__ Qf, const __half* __restrict__ Kf,
               const __half* __restrict__ Vf, __half* __restrict__ ctx16)
{
    extern __shared__ char sm8[];
    const uint32_t qs  = su32(sm8);
    const uint32_t kv0 = qs + 128 * QROW;                /* [K | V] stage 0 */

    const int tid = threadIdx.x, lane = tid & 31, wid = tid >> 5;
    const int bh = blockIdx.y, qb = blockIdx.x;
    const int g = lane >> 2, t = lane & 3;

    const __half* qg = Qf + ((size_t)bh * S_LEN + qb * 128) * HD;
    const __half* kg = Kf + (size_t)bh * S_LEN * HD;
    const __half* vg = Vf + (size_t)bh * S_LEN * HD;

    auto load_kv = [&](int j, int buf) {
        const uint32_t ks = kv0 + (uint32_t)buf * KV_STAGE;
        const uint32_t vs = ks + 64u * QROW;
        for (int i = tid; i < 1024; i += 256) {
            const int r = i >> 4, cc = i & 15;
            const size_t go = (size_t)(j * 64 + r) * HD + cc * 8;
            cpasync16(ks + r * QROW + cc * 16, kg + go);
            cpasync16(vs + r * QROW + cc * 16, vg + go);
        }
        asm volatile("cp.async.commit_group;" ::: "memory");
    };

    // Prologue: Q + KV(0) in group 0
    for (int i = tid; i < 2048; i += 256) {
        const int r = i >> 4, cc = i & 15;
        cpasync16(qs + r * QROW + cc * 16, qg + (size_t)r * HD + cc * 8);
    }
    {
        const uint32_t ks = kv0;
        const uint32_t vs = ks + 64u * QROW;
        for (int i = tid; i < 1024; i += 256) {
            const int r = i >> 4, cc = i & 15;
            const size_t go = (size_t)(r) * HD + cc * 8;
            cpasync16(ks + r * QROW + cc * 16, kg + go);
            cpasync16(vs + r * QROW + cc * 16, vg + go);
        }
    }
    asm volatile("cp.async.commit_group;" ::: "memory");

    float acc[16][4];
#pragma unroll
    for (int i = 0; i < 16; i++)
#pragma unroll
        for (int q = 0; q < 4; q++) acc[i][q] = 0.f;
    float m0 = NEG_BIG, m1 = NEG_BIG, l0 = 0.f, l1 = 0.f;

    const uint32_t aB = qs + (uint32_t)(wid * 16 + (lane & 15)) * QROW + (uint32_t)(lane >> 4) * 16u;
    const uint32_t bOff = (uint32_t)(lane & 15) * QROW + (uint32_t)(lane >> 4) * 16u;

    const int nj = S_LEN / 64;
#pragma unroll 1
    for (int j = 0; j < nj; j++) {
        if (j + 1 < nj) {
            load_kv(j + 1, (j + 1) & 1);
            asm volatile("cp.async.wait_group 1;" ::: "memory");
        } else {
            asm volatile("cp.async.wait_group 0;" ::: "memory");
        }
        __syncthreads();

        const uint32_t ks = kv0 + (uint32_t)(j & 1) * KV_STAGE;
        const uint32_t vs = ks + 64u * QROW;
        const uint32_t bB = ks + bOff;
        const uint32_t vB = vs + bOff;

        float cs[8][4];
#pragma unroll
        for (int i = 0; i < 8; i++)
#pragma unroll
            for (int q = 0; q < 4; q++) cs[i][q] = 0.f;
#pragma unroll
        for (int kd = 0; kd < 8; kd++) {
            uint32_t Aq[4];
            ldm_x4(Aq, aB + kd * 32u);
#pragma unroll
            for (int p = 0; p < 4; p++) {
                uint32_t Bq[4];
                ldm_x4(Bq, bB + (uint32_t)p * 16u * QROW + kd * 32u);
                mma16816(cs[2 * p],     Aq, Bq[0], Bq[2]);
                mma16816(cs[2 * p + 1], Aq, Bq[1], Bq[3]);
            }
        }

        float rm0 = m0, rm1 = m1;
#pragma unroll
        for (int i = 0; i < 8; i++) {
            rm0 = fmaxf(rm0, fmaxf(cs[i][0], cs[i][1]));
            rm1 = fmaxf(rm1, fmaxf(cs[i][2], cs[i][3]));
        }
        rm0 = fmaxf(rm0, __shfl_xor_sync(0xffffffffu, rm0, 1));
        rm0 = fmaxf(rm0, __shfl_xor_sync(0xffffffffu, rm0, 2));
        rm1 = fmaxf(rm1, __shfl_xor_sync(0xffffffffu, rm1, 1));
        rm1 = fmaxf(rm1, __shfl_xor_sync(0xffffffffu, rm1, 2));
        const float al0 = __expf(m0 - rm0);
        const float al1 = __expf(m1 - rm1);
        m0 = rm0; m1 = rm1;

        uint32_t ph[8][2];
        float s0 = 0.f, s1 = 0.f;
#pragma unroll
        for (int i = 0; i < 8; i++) {
            const float e0 = __expf(cs[i][0] - m0);
            const float e1 = __expf(cs[i][1] - m0);
            const float e2 = __expf(cs[i][2] - m1);
            const float e3 = __expf(cs[i][3] - m1);
            s0 += e0 + e1;  s1 += e2 + e3;
            ph[i][0] = packh2(e0, e1);
            ph[i][1] = packh2(e2, e3);
        }
        s0 += __shfl_xor_sync(0xffffffffu, s0, 1);
        s0 += __shfl_xor_sync(0xffffffffu, s0, 2);
        s1 += __shfl_xor_sync(0xffffffffu, s1, 1);
        s1 += __shfl_xor_sync(0xffffffffu, s1, 2);
        l0 = l0 * al0 + s0;
        l1 = l1 * al1 + s1;

#pragma unroll
        for (int i = 0; i < 16; i++) {
            acc[i][0] *= al0; acc[i][1] *= al0;
            acc[i][2] *= al1; acc[i][3] *= al1;
        }

#pragma unroll
        for (int kc = 0; kc < 4; kc++) {
            uint32_t Ap[4] = { ph[2 * kc][0], ph[2 * kc][1], ph[2 * kc + 1][0], ph[2 * kc + 1][1] };
#pragma unroll
            for (int dn = 0; dn < 8; dn++) {
                uint32_t Bv[4];
                ldm_x4t(Bv, vB + (uint32_t)kc * 16u * QROW + (uint32_t)dn * 32u);
                mma16816(acc[2 * dn],     Ap, Bv[0], Bv[1]);
                mma16816(acc[2 * dn + 1], Ap, Bv[2], Bv[3]);
            }
        }
        __syncthreads();
    }

    // Epilogue: ctx plain fp16 [tok][h*128+d]
    const float il0 = 1.f / l0, il1 = 1.f / l1;
    const int b = bh >> 5, h = bh & 31;
    const int tok0 = b * S_LEN + qb * 128 + wid * 16 + g;
#pragma unroll
    for (int nt = 0; nt < 16; nt++) {
        const int d0 = (nt >> 1) * 16 + (nt & 1) * 8 + 2 * t;
#pragma unroll
        for (int half8 = 0; half8 < 2; half8++) {
            const int tok = tok0 + half8 * 8;
            const float il = half8 ? il1 : il0;
            const float v0 = acc[nt][2 * half8 + 0] * il;
            const float v1 = acc[nt][2 * half8 + 1] * il;
            *(__half2*)(ctx16 + (size_t)tok * HID + h * HD + d0) = __floats2half2_rn(v0, v1);
        }
    }
}

// ---------------------------------------------------------------------------
// Host side
// ---------------------------------------------------------------------------
extern "C" void kernel_launch(void* const* d_in, const int* in_sizes, int n_in,
                              void* d_out, int out_size)
{
    (void)in_sizes; (void)n_in; (void)out_size;
    const float* x    = (const float*)d_in[0];
    const float* qkvw = (const float*)d_in[1];
    const float* qkvb = (const float*)d_in[2];
    const float* ow   = (const float*)d_in[3];
    const float* ob   = (const float*)d_in[4];
    float* out = (float*)d_out;

    __half *qf, *kf, *vf, *x16, *ctx16, *wq, *wo;
    cudaGetSymbolAddress((void**)&qf,    g_qf);
    cudaGetSymbolAddress((void**)&kf,    g_kf);
    cudaGetSymbolAddress((void**)&vf,    g_vf);
    cudaGetSymbolAddress((void**)&x16,   g_x16);
    cudaGetSymbolAddress((void**)&ctx16, g_ctx16);
    cudaGetSymbolAddress((void**)&wq,    g_wq);
    cudaGetSymbolAddress((void**)&wo,    g_wo);

    cudaFuncSetAttribute(gemm_f16s<1>, cudaFuncAttributeMaxDynamicSharedMemorySize, GEMM_DSMEM);
    cudaFuncSetAttribute(gemm_f16s<0>, cudaFuncAttributeMaxDynamicSharedMemorySize, GEMM_DSMEM);
    cudaFuncSetAttribute(flash_mma, cudaFuncAttributeMaxDynamicSharedMemorySize, FL_SMEM);

    const int n4 = M_ROWS * HID / 4;

    // 1) pack x and weights to fp16
    pack_a<<<(n4 + 255) / 256, 256>>>(x, x16, n4);
    pack_w<<<dim3(QKV_N / 32, HID / 32), dim3(32, 8)>>>(qkvw, wq, QKV_N);
    pack_w<<<dim3(HID / 32, HID / 32), dim3(32, 8)>>>(ow, wo, HID);

    // 2) q,k,v (fp16, q pre-scaled) = x @ W_qkv + b  (R12 grid: N fastest)
    gemm_f16s<1><<<dim3(QKV_N / 128, M_ROWS / 128), 256, GEMM_DSMEM>>>(
        x16, wq, qkvb, nullptr, QKV_N, qf, kf, vf);

    // 3) tensor-core flash attention -> ctx16 (fp16), double-buffered K/V
    flash_mma<<<dim3(S_LEN / 128, BATCH * NHEADS), 256, FL_SMEM>>>(qf, kf, vf, ctx16);

    // 4) out = ctx @ W_o + b
    gemm_f16s<0><<<dim3(HID / 128, M_ROWS / 128), 256, GEMM_DSMEM>>>(
        ctx16, wo, ob, out, HID, nullptr, nullptr, nullptr);
}